// round 1
// baseline (speedup 1.0000x reference)
#include <cuda_runtime.h>
#include <math.h>

#define N_NODES   100000
#define N_FEAT    128
#define N_CLASSES 40
#define N_EDGES   1600000
#define K_HOPS    2

// ---- scratch (no allocation allowed; __device__ globals) ----
__device__ float g_bufA[N_NODES * N_CLASSES];   // 16 MB
__device__ float g_bufB[N_NODES * N_CLASSES];   // 16 MB
__device__ int   g_deg[N_NODES];
__device__ float g_dis[N_NODES];
__device__ float g_norm[N_EDGES];               // 6.4 MB

// ---------------------------------------------------------------------------
__global__ void k_zero_deg() {
    int i = blockIdx.x * blockDim.x + threadIdx.x;
    if (i < N_NODES) g_deg[i] = 0;
}

__global__ void k_hist(const int* __restrict__ dst, int E) {
    int e = blockIdx.x * blockDim.x + threadIdx.x;
    if (e < E) atomicAdd(&g_deg[dst[e]], 1);
}

__global__ void k_dis() {
    int i = blockIdx.x * blockDim.x + threadIdx.x;
    if (i < N_NODES) g_dis[i] = rsqrtf((float)g_deg[i] + 1.0f);  // +1 = self loop
}

__global__ void k_norm(const int* __restrict__ src, const int* __restrict__ dst, int E) {
    int e = blockIdx.x * blockDim.x + threadIdx.x;
    if (e < E) g_norm[e] = g_dis[src[e]] * g_dis[dst[e]];
}

// ---- y0 = x @ W  (thread per node, W in shared) ---------------------------
__global__ void k_gemm(const float* __restrict__ x, const float* __restrict__ W) {
    __shared__ float Ws[N_FEAT * N_CLASSES];  // 20 KB
    for (int i = threadIdx.x; i < N_FEAT * N_CLASSES; i += blockDim.x)
        Ws[i] = W[i];
    __syncthreads();

    int node = blockIdx.x * blockDim.x + threadIdx.x;
    if (node >= N_NODES) return;

    float acc[N_CLASSES];
#pragma unroll
    for (int c = 0; c < N_CLASSES; c++) acc[c] = 0.0f;

    const float4* xr = (const float4*)(x + (size_t)node * N_FEAT);
#pragma unroll 1
    for (int k0 = 0; k0 < N_FEAT; k0 += 4) {
        float4 xv = __ldg(&xr[k0 >> 2]);
#pragma unroll
        for (int c = 0; c < N_CLASSES; c++) {
            acc[c] += xv.x * Ws[(k0 + 0) * N_CLASSES + c]
                    + xv.y * Ws[(k0 + 1) * N_CLASSES + c]
                    + xv.z * Ws[(k0 + 2) * N_CLASSES + c]
                    + xv.w * Ws[(k0 + 3) * N_CLASSES + c];
        }
    }
    float* out = g_bufA + (size_t)node * N_CLASSES;
#pragma unroll
    for (int c = 0; c < N_CLASSES; c++) out[c] = acc[c];
}

// ---- hop init: out[i] = dis[i]^2 * in[i]  (self-loop term) ---------------
__global__ void k_selfinit(int aToB) {
    const int CHUNKS = N_CLASSES / 4;  // 10
    unsigned idx = blockIdx.x * blockDim.x + threadIdx.x;
    if (idx >= (unsigned)(N_NODES * CHUNKS)) return;
    unsigned i = idx / CHUNKS;
    const float4* in  = (const float4*)(aToB ? g_bufA : g_bufB);
    float4*       out = (float4*)(aToB ? g_bufB : g_bufA);
    float s = g_dis[i];
    s *= s;
    float4 v = in[idx];
    v.x *= s; v.y *= s; v.z *= s; v.w *= s;
    out[idx] = v;
}

// ---- hop scatter: out[dst] += norm * in[src], one thread per (edge,chunk) -
__global__ void k_scatter(const int* __restrict__ src, const int* __restrict__ dst,
                          int E, int aToB) {
    const unsigned CHUNKS = N_CLASSES / 4;  // 10
    unsigned idx = blockIdx.x * blockDim.x + threadIdx.x;
    if (idx >= (unsigned)E * CHUNKS) return;
    unsigned e = idx / CHUNKS;
    unsigned c = idx % CHUNKS;

    const float* in  = aToB ? g_bufA : g_bufB;
    float*       out = aToB ? g_bufB : g_bufA;

    int s = src[e];
    int d = dst[e];
    float w = g_norm[e];

    const float4* ip = (const float4*)(in + (size_t)s * N_CLASSES) + c;
    float4 v = __ldg(ip);
    float* op = out + (size_t)d * N_CLASSES + c * 4;
    asm volatile("red.global.add.v4.f32 [%0], {%1,%2,%3,%4};"
                 :: "l"(op), "f"(v.x * w), "f"(v.y * w), "f"(v.z * w), "f"(v.w * w)
                 : "memory");
}

// ---- epilogue: logits = y + b; out = log_softmax(logits) ------------------
__global__ void k_final(const float* __restrict__ b, float* __restrict__ out, int finalInA) {
    int i = blockIdx.x * blockDim.x + threadIdx.x;
    if (i >= N_NODES) return;
    const float* y = (finalInA ? g_bufA : g_bufB) + (size_t)i * N_CLASSES;

    float l[N_CLASSES];
    float m = -INFINITY;
#pragma unroll
    for (int c = 0; c < N_CLASSES; c++) {
        l[c] = y[c] + b[c];
        m = fmaxf(m, l[c]);
    }
    float sum = 0.0f;
#pragma unroll
    for (int c = 0; c < N_CLASSES; c++) sum += expf(l[c] - m);
    float lse = m + logf(sum);

    float* o = out + (size_t)i * N_CLASSES;
#pragma unroll
    for (int c = 0; c < N_CLASSES; c++) o[c] = l[c] - lse;
}

// ---------------------------------------------------------------------------
extern "C" void kernel_launch(void* const* d_in, const int* in_sizes, int n_in,
                              void* d_out, int out_size) {
    const float* x  = (const float*)d_in[0];
    const float* W  = (const float*)d_in[1];
    const float* b  = (const float*)d_in[2];
    const int*   ei = (const int*)d_in[3];
    // d_in[4] is K (scalar, = 2); fixed as K_HOPS.

    const int E = in_sizes[3] / 2;
    const int* src = ei;
    const int* dst = ei + E;

    const int T = 256;
    // degree + normalization
    k_zero_deg<<<(N_NODES + T - 1) / T, T>>>();
    k_hist<<<(E + T - 1) / T, T>>>(dst, E);
    k_dis<<<(N_NODES + T - 1) / T, T>>>();
    k_norm<<<(E + T - 1) / T, T>>>(src, dst, E);

    // project first: y0 = x @ W  -> bufA
    k_gemm<<<(N_NODES + T - 1) / T, T>>>(x, W);

    // K hops of propagation in 40-dim space (ping-pong A<->B)
    int aToB = 1;
    for (int h = 0; h < K_HOPS; h++) {
        unsigned nodework = N_NODES * (N_CLASSES / 4);
        unsigned edgework = (unsigned)E * (N_CLASSES / 4);
        k_selfinit<<<(nodework + T - 1) / T, T>>>(aToB);
        k_scatter<<<(edgework + T - 1) / T, T>>>(src, dst, E, aToB);
        aToB ^= 1;
    }
    // after even K, result is back in bufA (aToB==1 => final in A)
    k_final<<<(N_NODES + T - 1) / T, T>>>(b, (float*)d_out, aToB);
}